// round 1
// baseline (speedup 1.0000x reference)
#include <cuda_runtime.h>
#include <stdint.h>

// Problem constants
#define SB   2
#define SS   2048
#define SE   1024
#define SH   16
#define SDK  64
#define MTOT (SB * SS)   // 4096

// Scratch (device globals: allocation-free rule)
__device__ float g_Q[MTOT * SE];
__device__ float g_K[MTOT * SE];
__device__ float g_V[MTOT * SE];
__device__ float g_A[MTOT * SE];
__device__ int   g_mask_kind;   // 0 = u8, 1 = i32, 2 = f32

// ---------------------------------------------------------------------------
// Mask dtype detection (bool arrays may arrive as u8, i32 or f32 buffers).
// Deterministic: same input -> same flag every call.
// ---------------------------------------------------------------------------
__global__ void detect_mask_kind_kernel(const unsigned char* __restrict__ m) {
    __shared__ int s1, s3f;
    if (threadIdx.x == 0) { s1 = 0; s3f = 0; }
    __syncthreads();
    int n1 = 0, n3f = 0;
    // sample first 64KB of the buffer (exists for all candidate dtypes)
    for (int i = threadIdx.x * 4; i < 65536; i += 256 * 4) {
        n1  += (m[i + 1] != 0);         // nonzero only if plain u8 storage
        n3f += (m[i + 3] == 0x3F);      // 1.0f high byte pattern
    }
    atomicAdd(&s1, n1);
    atomicAdd(&s3f, n3f);
    __syncthreads();
    if (threadIdx.x == 0) {
        int kind = 0;                    // u8
        if (s1 == 0) kind = (s3f > 0) ? 2 : 1;   // f32 : i32
        g_mask_kind = kind;
    }
}

__device__ __forceinline__ bool mask_at(const void* m, long idx, int kind) {
    if (kind == 0) return ((const unsigned char*)m)[idx] != 0;
    if (kind == 1) return ((const int*)m)[idx] != 0;
    return ((const float*)m)[idx] != 0.0f;
}

// ---------------------------------------------------------------------------
// SGEMM: C[M,N] = A[M,K] @ W[N,K]^T + bias[N]    (M=4096, N=K=1024)
// 128x128 block tile, BK=16, 256 threads, 8x8 per-thread tile,
// double-buffered shared memory with register prefetch.
// ---------------------------------------------------------------------------
#define GBM 128
#define GBN 128
#define GBK 16

__device__ __forceinline__ void gemm_body(
    const float* __restrict__ A, const float* __restrict__ W,
    const float* __restrict__ bias, float* __restrict__ C)
{
    __shared__ float As[2][GBK][GBM];
    __shared__ float Bs[2][GBK][GBN];

    const int tid = threadIdx.x;
    const int tx  = tid & 15;
    const int ty  = tid >> 4;
    const int bm  = blockIdx.y * GBM;
    const int bn  = blockIdx.x * GBN;

    const int lr = tid >> 2;          // 0..63
    const int lc = (tid & 3) << 2;    // 0,4,8,12 (k offset)

    const float* pa0 = A + (long)(bm + lr)      * SE + lc;
    const float* pa1 = A + (long)(bm + lr + 64) * SE + lc;
    const float* pb0 = W + (long)(bn + lr)      * SE + lc;
    const float* pb1 = W + (long)(bn + lr + 64) * SE + lc;

    float acc[8][8];
    #pragma unroll
    for (int i = 0; i < 8; i++)
        #pragma unroll
        for (int j = 0; j < 8; j++) acc[i][j] = 0.0f;

    float4 fa0 = *(const float4*)pa0;
    float4 fa1 = *(const float4*)pa1;
    float4 fb0 = *(const float4*)pb0;
    float4 fb1 = *(const float4*)pb1;

    As[0][lc + 0][lr]      = fa0.x; As[0][lc + 1][lr]      = fa0.y;
    As[0][lc + 2][lr]      = fa0.z; As[0][lc + 3][lr]      = fa0.w;
    As[0][lc + 0][lr + 64] = fa1.x; As[0][lc + 1][lr + 64] = fa1.y;
    As[0][lc + 2][lr + 64] = fa1.z; As[0][lc + 3][lr + 64] = fa1.w;
    Bs[0][lc + 0][lr]      = fb0.x; Bs[0][lc + 1][lr]      = fb0.y;
    Bs[0][lc + 2][lr]      = fb0.z; Bs[0][lc + 3][lr]      = fb0.w;
    Bs[0][lc + 0][lr + 64] = fb1.x; Bs[0][lc + 1][lr + 64] = fb1.y;
    Bs[0][lc + 2][lr + 64] = fb1.z; Bs[0][lc + 3][lr + 64] = fb1.w;
    __syncthreads();

    const int KT = SE / GBK;   // 64
    int buf = 0;
    #pragma unroll 1
    for (int kt = 0; kt < KT; kt++) {
        if (kt + 1 < KT) {
            const int off = (kt + 1) * GBK;
            fa0 = *(const float4*)(pa0 + off);
            fa1 = *(const float4*)(pa1 + off);
            fb0 = *(const float4*)(pb0 + off);
            fb1 = *(const float4*)(pb1 + off);
        }
        #pragma unroll
        for (int kk = 0; kk < GBK; kk++) {
            float4 a0 = *(const float4*)&As[buf][kk][ty * 8];
            float4 a1 = *(const float4*)&As[buf][kk][ty * 8 + 4];
            float4 b0 = *(const float4*)&Bs[buf][kk][tx * 8];
            float4 b1 = *(const float4*)&Bs[buf][kk][tx * 8 + 4];
            float ar[8] = {a0.x, a0.y, a0.z, a0.w, a1.x, a1.y, a1.z, a1.w};
            float br[8] = {b0.x, b0.y, b0.z, b0.w, b1.x, b1.y, b1.z, b1.w};
            #pragma unroll
            for (int i = 0; i < 8; i++)
                #pragma unroll
                for (int j = 0; j < 8; j++)
                    acc[i][j] += ar[i] * br[j];
        }
        if (kt + 1 < KT) {
            const int nb = buf ^ 1;
            As[nb][lc + 0][lr]      = fa0.x; As[nb][lc + 1][lr]      = fa0.y;
            As[nb][lc + 2][lr]      = fa0.z; As[nb][lc + 3][lr]      = fa0.w;
            As[nb][lc + 0][lr + 64] = fa1.x; As[nb][lc + 1][lr + 64] = fa1.y;
            As[nb][lc + 2][lr + 64] = fa1.z; As[nb][lc + 3][lr + 64] = fa1.w;
            Bs[nb][lc + 0][lr]      = fb0.x; Bs[nb][lc + 1][lr]      = fb0.y;
            Bs[nb][lc + 2][lr]      = fb0.z; Bs[nb][lc + 3][lr]      = fb0.w;
            Bs[nb][lc + 0][lr + 64] = fb1.x; Bs[nb][lc + 1][lr + 64] = fb1.y;
            Bs[nb][lc + 2][lr + 64] = fb1.z; Bs[nb][lc + 3][lr + 64] = fb1.w;
        }
        __syncthreads();
        buf ^= 1;
    }

    float bj[8];
    #pragma unroll
    for (int j = 0; j < 8; j++) bj[j] = bias[bn + tx * 8 + j];

    #pragma unroll
    for (int i = 0; i < 8; i++) {
        float* cp = C + (long)(bm + ty * 8 + i) * SE + bn + tx * 8;
        float4 o0, o1;
        o0.x = acc[i][0] + bj[0]; o0.y = acc[i][1] + bj[1];
        o0.z = acc[i][2] + bj[2]; o0.w = acc[i][3] + bj[3];
        o1.x = acc[i][4] + bj[4]; o1.y = acc[i][5] + bj[5];
        o1.z = acc[i][6] + bj[6]; o1.w = acc[i][7] + bj[7];
        *(float4*)cp       = o0;
        *(float4*)(cp + 4) = o1;
    }
}

// Fused QKV projection: blockIdx.z selects which of the three GEMMs.
__global__ __launch_bounds__(256, 2)
void qkv_gemm_kernel(const float* __restrict__ x,
                     const float* __restrict__ Wq, const float* __restrict__ bq,
                     const float* __restrict__ Wk, const float* __restrict__ bk,
                     const float* __restrict__ Wv, const float* __restrict__ bv)
{
    const float* W; const float* bias; float* C;
    if (blockIdx.z == 0)      { W = Wq; bias = bq; C = g_Q; }
    else if (blockIdx.z == 1) { W = Wk; bias = bk; C = g_K; }
    else                      { W = Wv; bias = bv; C = g_V; }
    gemm_body(x, W, bias, C);
}

__global__ __launch_bounds__(256, 2)
void out_gemm_kernel(const float* __restrict__ Wo, const float* __restrict__ bo,
                     float* __restrict__ out)
{
    gemm_body(g_A, Wo, bo, out);
}

// ---------------------------------------------------------------------------
// Flash-style attention. One block handles (b, h, 64-query tile).
// 256 threads as 16x16 grid, 4x4 per-thread fragments.
// Online softmax state (m, l) kept redundantly in registers per row-group.
// Shared: Qt[d][q], Kt[d][k], Vs[k][d], Pt[k][q], each [64][68] fp32.
// ---------------------------------------------------------------------------
#define APAD 68
#define ATT_SMEM (4 * 64 * APAD * sizeof(float))

__global__ __launch_bounds__(256, 2)
void attn_kernel(const float* __restrict__ Qb, const float* __restrict__ Kb,
                 const float* __restrict__ Vb, const void* __restrict__ mask,
                 float* __restrict__ Ob)
{
    extern __shared__ float sm[];
    float* Qt = sm;                    // [64][APAD], d-major: Qt[d*APAD + q]
    float* Kt = sm + 64 * APAD;        // Kt[d*APAD + k]
    float* Vs = sm + 2 * 64 * APAD;    // Vs[k*APAD + d]
    float* Pt = sm + 3 * 64 * APAD;    // Pt[k*APAD + q]

    const int tid = threadIdx.x;
    const int tx  = tid & 15;
    const int ty  = tid >> 4;
    const int q0   = blockIdx.x * 64;
    const int h    = blockIdx.y;
    const int b    = blockIdx.z;
    const int row0 = b * SS;
    const int col0 = h * SDK;
    const int mk   = g_mask_kind;

    // Load Q tile transposed into Qt[d][q]
    {
        const int r  = tid >> 2;        // q within tile: 0..63
        const int c4 = tid & 3;
        const float* src = Qb + (long)(row0 + q0 + r) * SE + col0;
        #pragma unroll
        for (int cc = c4; cc < 16; cc += 4) {
            float4 v = *(const float4*)(src + cc * 4);
            Qt[(cc * 4 + 0) * APAD + r] = v.x;
            Qt[(cc * 4 + 1) * APAD + r] = v.y;
            Qt[(cc * 4 + 2) * APAD + r] = v.z;
            Qt[(cc * 4 + 3) * APAD + r] = v.w;
        }
    }

    float o[4][4];
    float mrow[4], lrow[4];
    #pragma unroll
    for (int i = 0; i < 4; i++) {
        mrow[i] = -3.0e38f;
        lrow[i] = 0.0f;
        #pragma unroll
        for (int j = 0; j < 4; j++) o[i][j] = 0.0f;
    }

    const long mbase = (long)b * SS * SS;

    for (int kt = 0; kt < SS / 64; kt++) {
        const int k0 = kt * 64;
        __syncthreads();   // prev phase-3 reads of Kt/Vs/Pt done (also orders Qt on iter 0)

        // Load K tile transposed Kt[d][k] and V tile Vs[k][d]
        {
            const int r  = tid >> 2;
            const int c4 = tid & 3;
            const float* ksrc = Kb + (long)(row0 + k0 + r) * SE + col0;
            const float* vsrc = Vb + (long)(row0 + k0 + r) * SE + col0;
            #pragma unroll
            for (int cc = c4; cc < 16; cc += 4) {
                float4 kv = *(const float4*)(ksrc + cc * 4);
                Kt[(cc * 4 + 0) * APAD + r] = kv.x;
                Kt[(cc * 4 + 1) * APAD + r] = kv.y;
                Kt[(cc * 4 + 2) * APAD + r] = kv.z;
                Kt[(cc * 4 + 3) * APAD + r] = kv.w;
                float4 vv = *(const float4*)(vsrc + cc * 4);
                *(float4*)&Vs[r * APAD + cc * 4] = vv;
            }
        }
        __syncthreads();

        // Phase 1: S[q=ty*4+i][k=tx*4+j] = sum_d Qt[d][q] * Kt[d][k]
        float s[4][4];
        #pragma unroll
        for (int i = 0; i < 4; i++)
            #pragma unroll
            for (int j = 0; j < 4; j++) s[i][j] = 0.0f;

        #pragma unroll 8
        for (int d = 0; d < 64; d++) {
            float4 aq = *(const float4*)&Qt[d * APAD + ty * 4];
            float4 ak = *(const float4*)&Kt[d * APAD + tx * 4];
            float qa[4] = {aq.x, aq.y, aq.z, aq.w};
            float ka[4] = {ak.x, ak.y, ak.z, ak.w};
            #pragma unroll
            for (int i = 0; i < 4; i++)
                #pragma unroll
                for (int j = 0; j < 4; j++)
                    s[i][j] += qa[i] * ka[j];
        }

        // Phase 2: mask + online softmax; write Pt[k][q]
        #pragma unroll
        for (int i = 0; i < 4; i++) {
            const int q = q0 + ty * 4 + i;
            const long mrb = mbase + (long)q * SS + k0 + tx * 4;
            float sv[4];
            #pragma unroll
            for (int j = 0; j < 4; j++) {
                bool msk = mask_at(mask, mrb + j, mk);
                sv[j] = msk ? -1.0e9f : s[i][j] * 0.125f;
            }
            float mx = fmaxf(fmaxf(sv[0], sv[1]), fmaxf(sv[2], sv[3]));
            #pragma unroll
            for (int off = 1; off < 16; off <<= 1)
                mx = fmaxf(mx, __shfl_xor_sync(0xffffffffu, mx, off));
            const float mnew = fmaxf(mrow[i], mx);
            const float sc   = __expf(mrow[i] - mnew);
            float psum = 0.0f;
            #pragma unroll
            for (int j = 0; j < 4; j++) {
                float p = __expf(sv[j] - mnew);
                psum += p;
                Pt[(tx * 4 + j) * APAD + ty * 4 + i] = p;
            }
            #pragma unroll
            for (int off = 1; off < 16; off <<= 1)
                psum += __shfl_xor_sync(0xffffffffu, psum, off);
            lrow[i] = lrow[i] * sc + psum;
            mrow[i] = mnew;
            #pragma unroll
            for (int j = 0; j < 4; j++) o[i][j] *= sc;
        }
        __syncthreads();

        // Phase 3: O[q][d=tx*4+j] += sum_k Pt[k][q] * Vs[k][d]
        #pragma unroll 8
        for (int k = 0; k < 64; k++) {
            float4 ap = *(const float4*)&Pt[k * APAD + ty * 4];
            float4 av = *(const float4*)&Vs[k * APAD + tx * 4];
            float pa[4] = {ap.x, ap.y, ap.z, ap.w};
            float va[4] = {av.x, av.y, av.z, av.w};
            #pragma unroll
            for (int i = 0; i < 4; i++)
                #pragma unroll
                for (int j = 0; j < 4; j++)
                    o[i][j] += pa[i] * va[j];
        }
    }

    // Epilogue: normalize by l and write to [B,S,E] attention buffer
    #pragma unroll
    for (int i = 0; i < 4; i++) {
        const float inv = 1.0f / lrow[i];
        float4 v;
        v.x = o[i][0] * inv; v.y = o[i][1] * inv;
        v.z = o[i][2] * inv; v.w = o[i][3] * inv;
        *(float4*)&Ob[(long)(row0 + q0 + ty * 4 + i) * SE + col0 + tx * 4] = v;
    }
}

// ---------------------------------------------------------------------------
// Launch
// ---------------------------------------------------------------------------
extern "C" void kernel_launch(void* const* d_in, const int* in_sizes, int n_in,
                              void* d_out, int out_size)
{
    const float* x    = (const float*)d_in[0];
    const void*  mask = d_in[1];
    const float* Wq   = (const float*)d_in[2];
    const float* bq   = (const float*)d_in[3];
    const float* Wk   = (const float*)d_in[4];
    const float* bk   = (const float*)d_in[5];
    const float* Wv   = (const float*)d_in[6];
    const float* bv   = (const float*)d_in[7];
    const float* Wo   = (const float*)d_in[8];
    const float* bo   = (const float*)d_in[9];
    float* out = (float*)d_out;

    float *Qb, *Kb, *Vb, *Ab;
    cudaGetSymbolAddress((void**)&Qb, g_Q);
    cudaGetSymbolAddress((void**)&Kb, g_K);
    cudaGetSymbolAddress((void**)&Vb, g_V);
    cudaGetSymbolAddress((void**)&Ab, g_A);

    detect_mask_kind_kernel<<<1, 256>>>((const unsigned char*)mask);

    dim3 gqkv(SE / GBN, MTOT / GBM, 3);
    qkv_gemm_kernel<<<gqkv, 256>>>(x, Wq, bq, Wk, bk, Wv, bv);

    cudaFuncSetAttribute(attn_kernel,
                         cudaFuncAttributeMaxDynamicSharedMemorySize,
                         (int)ATT_SMEM);
    dim3 gat(SS / 64, SH, SB);
    attn_kernel<<<gat, 256, ATT_SMEM>>>(Qb, Kb, Vb, mask, Ab);

    dim3 gout(SE / GBN, MTOT / GBM);
    out_gemm_kernel<<<gout, 256>>>(Wo, bo, out);
}

// round 3
// speedup vs baseline: 1.3575x; 1.3575x over previous
#include <cuda_runtime.h>
#include <cuda_bf16.h>
#include <stdint.h>

// Problem constants
#define SB   2
#define SS   2048
#define SE   1024
#define SH   16
#define SDK  64
#define MTOT (SB * SS)   // 4096

// Scratch (device globals: allocation-free rule)
__device__ float g_Q[MTOT * SE];
__device__ float g_K[MTOT * SE];
__device__ float g_V[MTOT * SE];
__device__ float g_A[MTOT * SE];
__device__ __nv_bfloat16 g_xhi[MTOT * SE];
__device__ __nv_bfloat16 g_xlo[MTOT * SE];
__device__ __nv_bfloat16 g_ahi[MTOT * SE];
__device__ __nv_bfloat16 g_alo[MTOT * SE];
__device__ __nv_bfloat16 g_whi[4 * SE * SE];
__device__ __nv_bfloat16 g_wlo[4 * SE * SE];
__device__ int   g_mask_kind;   // 0 = u8, 1 = i32, 2 = f32

// ---------------------------------------------------------------------------
// Helpers
// ---------------------------------------------------------------------------
__device__ __forceinline__ uint32_t smem_u32(const void* p) {
    uint32_t a;
    asm("{ .reg .u64 t; cvta.to.shared.u64 t, %1; cvt.u32.u64 %0, t; }"
        : "=r"(a) : "l"(p));
    return a;
}

__device__ __forceinline__ void cp_async16(uint32_t dst, const void* src) {
    asm volatile("cp.async.cg.shared.global [%0], [%1], 16;"
                 :: "r"(dst), "l"(src) : "memory");
}
__device__ __forceinline__ void cp_commit() {
    asm volatile("cp.async.commit_group;" ::: "memory");
}
template <int N>
__device__ __forceinline__ void cp_wait() {
    asm volatile("cp.async.wait_group %0;" :: "n"(N) : "memory");
}

__device__ __forceinline__ void ldm_x4(uint32_t* r, uint32_t addr) {
    asm volatile("ldmatrix.sync.aligned.m8n8.x4.shared.b16 {%0,%1,%2,%3}, [%4];"
                 : "=r"(r[0]), "=r"(r[1]), "=r"(r[2]), "=r"(r[3]) : "r"(addr));
}

__device__ __forceinline__ void mma_bf16(float* d, const uint32_t* a,
                                         uint32_t b0, uint32_t b1) {
    asm volatile(
        "mma.sync.aligned.m16n8k16.row.col.f32.bf16.bf16.f32 "
        "{%0,%1,%2,%3}, {%4,%5,%6,%7}, {%8,%9}, {%0,%1,%2,%3};"
        : "+f"(d[0]), "+f"(d[1]), "+f"(d[2]), "+f"(d[3])
        : "r"(a[0]), "r"(a[1]), "r"(a[2]), "r"(a[3]), "r"(b0), "r"(b1));
}

// ---------------------------------------------------------------------------
// Mask dtype detection
// ---------------------------------------------------------------------------
__global__ void detect_mask_kind_kernel(const unsigned char* __restrict__ m) {
    __shared__ int s1, s3f;
    if (threadIdx.x == 0) { s1 = 0; s3f = 0; }
    __syncthreads();
    int n1 = 0, n3f = 0;
    for (int i = threadIdx.x * 4; i < 65536; i += 256 * 4) {
        n1  += (m[i + 1] != 0);
        n3f += (m[i + 3] == 0x3F);
    }
    atomicAdd(&s1, n1);
    atomicAdd(&s3f, n3f);
    __syncthreads();
    if (threadIdx.x == 0) {
        int kind = 0;
        if (s1 == 0) kind = (s3f > 0) ? 2 : 1;
        g_mask_kind = kind;
    }
}

__device__ __forceinline__ bool mask_at(const void* m, long idx, int kind) {
    if (kind == 0) return ((const unsigned char*)m)[idx] != 0;
    if (kind == 1) return ((const int*)m)[idx] != 0;
    return ((const float*)m)[idx] != 0.0f;
}

// ---------------------------------------------------------------------------
// fp32 -> bf16 hi/lo split  (x = hi + lo + O(2^-16 x))
// ---------------------------------------------------------------------------
__global__ void split_kernel(const float* __restrict__ src,
                             __nv_bfloat16* __restrict__ hi,
                             __nv_bfloat16* __restrict__ lo, int n) {
    int i = (blockIdx.x * blockDim.x + threadIdx.x) * 4;
    if (i >= n) return;
    float4 v = *(const float4*)(src + i);
    __nv_bfloat16 h0 = __float2bfloat16_rn(v.x);
    __nv_bfloat16 h1 = __float2bfloat16_rn(v.y);
    __nv_bfloat16 h2 = __float2bfloat16_rn(v.z);
    __nv_bfloat16 h3 = __float2bfloat16_rn(v.w);
    __nv_bfloat162 hA, hB, lA, lB;
    hA.x = h0; hA.y = h1; hB.x = h2; hB.y = h3;
    lA.x = __float2bfloat16_rn(v.x - __bfloat162float(h0));
    lA.y = __float2bfloat16_rn(v.y - __bfloat162float(h1));
    lB.x = __float2bfloat16_rn(v.z - __bfloat162float(h2));
    lB.y = __float2bfloat16_rn(v.w - __bfloat162float(h3));
    *(__nv_bfloat162*)(hi + i)     = hA;
    *(__nv_bfloat162*)(hi + i + 2) = hB;
    *(__nv_bfloat162*)(lo + i)     = lA;
    *(__nv_bfloat162*)(lo + i + 2) = lB;
}

// ---------------------------------------------------------------------------
// bf16 3-pass MMA GEMM:  C[M,N] = A[M,K] @ W[N,K]^T + bias[N]
// Block tile 128x128, K-chunk 32, 8 warps (warp tile 64x32), cp.async 2-stage.
// SMEM row layout: 64B rows, 16B-chunk XOR swizzle  c' = c ^ ((r>>1)&3).
// ---------------------------------------------------------------------------
#define TM 128
#define TN 128
#define KC 32
#define NC (SE / KC)              // 32 chunks
#define BUFB  8192                // 128 rows x 64B
#define STAGEB (4 * BUFB)         // AH, AL, BH, BL
#define GEMM_SMEM (2 * STAGEB)    // 65536

__device__ __forceinline__ uint32_t sw_addr(uint32_t base, int r, int c16) {
    return base + r * 64 + ((c16 ^ ((r >> 1) & 3)) << 4);
}

__device__ __forceinline__ void mma_gemm_body(
    const __nv_bfloat16* __restrict__ Ahi, const __nv_bfloat16* __restrict__ Alo,
    const __nv_bfloat16* __restrict__ Whi, const __nv_bfloat16* __restrict__ Wlo,
    const float* __restrict__ bias, float* __restrict__ C)
{
    extern __shared__ char dynsm[];
    const uint32_t sb = smem_u32(dynsm);
    const int tid  = threadIdx.x;
    const int lane = tid & 31;
    const int wid  = tid >> 5;
    const int wm   = (wid >> 2) * 64;      // 0 or 64
    const int wn   = (wid & 3) * 32;       // 0,32,64,96
    const int bm   = blockIdx.y * TM;
    const int bn   = blockIdx.x * TN;

    const __nv_bfloat16* srcA[2] = { Ahi + (long)bm * SE, Alo + (long)bm * SE };
    const __nv_bfloat16* srcB[2] = { Whi + (long)bn * SE, Wlo + (long)bn * SE };

    float acc[4][4][4];
    #pragma unroll
    for (int i = 0; i < 4; i++)
        #pragma unroll
        for (int j = 0; j < 4; j++)
            #pragma unroll
            for (int k = 0; k < 4; k++) acc[i][j][k] = 0.0f;

    // issue loads for one chunk into stage buf
    auto issue = [&](int chunk, int buf) {
        const int kc0 = chunk * KC;
        #pragma unroll
        for (int q = 0; q < 8; q++) {
            const int mat    = q >> 1;              // 0:AH 1:AL 2:BH 3:BL
            const int within = (q & 1) * 256 + tid; // 0..511
            const int r   = within >> 2;
            const int c16 = within & 3;
            const __nv_bfloat16* s =
                (mat < 2 ? srcA[mat] : srcB[mat - 2]) + (long)r * SE + kc0 + c16 * 8;
            cp_async16(sw_addr(sb + buf * STAGEB + mat * BUFB, r, c16), s);
        }
        cp_commit();
    };

    issue(0, 0);

    for (int it = 0; it < NC; ++it) {
        const int buf = it & 1;
        if (it + 1 < NC) { issue(it + 1, buf ^ 1); cp_wait<1>(); }
        else             { cp_wait<0>(); }
        __syncthreads();

        const uint32_t AH = sb + buf * STAGEB;
        const uint32_t AL = AH + BUFB;
        const uint32_t BH = AH + 2 * BUFB;
        const uint32_t BL = AH + 3 * BUFB;

        #pragma unroll
        for (int ks = 0; ks < 2; ks++) {
            uint32_t ah[4][4], al[4][4], bh[2][4], bl[2][4];
            const int ar   = (lane & 15);
            const int ac16 = ks * 2 + (lane >> 4);
            #pragma unroll
            for (int i = 0; i < 4; i++) {
                const int r = wm + i * 16 + ar;
                ldm_x4(ah[i], sw_addr(AH, r, ac16));
                ldm_x4(al[i], sw_addr(AL, r, ac16));
            }
            const int br   = ((lane >> 4) << 3) + (lane & 7);
            const int bc16 = ks * 2 + ((lane >> 3) & 1);
            #pragma unroll
            for (int p = 0; p < 2; p++) {
                const int r = wn + p * 16 + br;
                ldm_x4(bh[p], sw_addr(BH, r, bc16));
                ldm_x4(bl[p], sw_addr(BL, r, bc16));
            }
            #pragma unroll
            for (int i = 0; i < 4; i++)
                #pragma unroll
                for (int j = 0; j < 4; j++) {
                    const int p = j >> 1, o = (j & 1) * 2;
                    mma_bf16(acc[i][j], ah[i], bh[p][o], bh[p][o + 1]);
                    mma_bf16(acc[i][j], ah[i], bl[p][o], bl[p][o + 1]);
                    mma_bf16(acc[i][j], al[i], bh[p][o], bh[p][o + 1]);
                }
        }
        __syncthreads();
    }

    // Epilogue: c-frag mapping row = lane/4 (+8), col = (lane%4)*2 (+1)
    #pragma unroll
    for (int j = 0; j < 4; j++) {
        const int gn = bn + wn + j * 8 + ((lane & 3) << 1);
        const float b0 = bias[gn], b1 = bias[gn + 1];
        #pragma unroll
        for (int i = 0; i < 4; i++) {
            const int gm = bm + wm + i * 16 + (lane >> 2);
            float2 v0 = { acc[i][j][0] + b0, acc[i][j][1] + b1 };
            float2 v1 = { acc[i][j][2] + b0, acc[i][j][3] + b1 };
            *(float2*)(C + (long)gm * SE + gn)       = v0;
            *(float2*)(C + (long)(gm + 8) * SE + gn) = v1;
        }
    }
}

__global__ __launch_bounds__(256, 1)
void qkv_gemm_kernel(const float* __restrict__ bq, const float* __restrict__ bk,
                     const float* __restrict__ bv)
{
    const float* bias; float* C; int z = blockIdx.z;
    if (z == 0)      { bias = bq; C = g_Q; }
    else if (z == 1) { bias = bk; C = g_K; }
    else             { bias = bv; C = g_V; }
    mma_gemm_body(g_xhi, g_xlo,
                  g_whi + (long)z * SE * SE, g_wlo + (long)z * SE * SE,
                  bias, C);
}

__global__ __launch_bounds__(256, 1)
void out_gemm_kernel(const float* __restrict__ bo, float* __restrict__ out)
{
    mma_gemm_body(g_ahi, g_alo,
                  g_whi + 3L * SE * SE, g_wlo + 3L * SE * SE,
                  bo, out);
}

// ---------------------------------------------------------------------------
// Flash-style attention (SIMT fp32, round-1 proven version).
// ---------------------------------------------------------------------------
#define APAD 68
#define ATT_SMEM (4 * 64 * APAD * sizeof(float))

__global__ __launch_bounds__(256, 2)
void attn_kernel(const float* __restrict__ Qb, const float* __restrict__ Kb,
                 const float* __restrict__ Vb, const void* __restrict__ mask,
                 float* __restrict__ Ob)
{
    extern __shared__ float sm[];
    float* Qt = sm;                    // [64][APAD], d-major
    float* Kt = sm + 64 * APAD;
    float* Vs = sm + 2 * 64 * APAD;
    float* Pt = sm + 3 * 64 * APAD;

    const int tid = threadIdx.x;
    const int tx  = tid & 15;
    const int ty  = tid >> 4;
    const int q0   = blockIdx.x * 64;
    const int h    = blockIdx.y;
    const int b    = blockIdx.z;
    const int row0 = b * SS;
    const int col0 = h * SDK;
    const int mk   = g_mask_kind;

    {
        const int r  = tid >> 2;
        const int c4 = tid & 3;
        const float* src = Qb + (long)(row0 + q0 + r) * SE + col0;
        #pragma unroll
        for (int cc = c4; cc < 16; cc += 4) {
            float4 v = *(const float4*)(src + cc * 4);
            Qt[(cc * 4 + 0) * APAD + r] = v.x;
            Qt[(cc * 4 + 1) * APAD + r] = v.y;
            Qt[(cc * 4 + 2) * APAD + r] = v.z;
            Qt[(cc * 4 + 3) * APAD + r] = v.w;
        }
    }

    float o[4][4];
    float mrow[4], lrow[4];
    #pragma unroll
    for (int i = 0; i < 4; i++) {
        mrow[i] = -3.0e38f;
        lrow[i] = 0.0f;
        #pragma unroll
        for (int j = 0; j < 4; j++) o[i][j] = 0.0f;
    }

    const long mbase = (long)b * SS * SS;

    for (int kt = 0; kt < SS / 64; kt++) {
        const int k0 = kt * 64;
        __syncthreads();

        {
            const int r  = tid >> 2;
            const int c4 = tid & 3;
            const float* ksrc = Kb + (long)(row0 + k0 + r) * SE + col0;
            const float* vsrc = Vb + (long)(row0 + k0 + r) * SE + col0;
            #pragma unroll
            for (int cc = c4; cc < 16; cc += 4) {
                float4 kv = *(const float4*)(ksrc + cc * 4);
                Kt[(cc * 4 + 0) * APAD + r] = kv.x;
                Kt[(cc * 4 + 1) * APAD + r] = kv.y;
                Kt[(cc * 4 + 2) * APAD + r] = kv.z;
                Kt[(cc * 4 + 3) * APAD + r] = kv.w;
                float4 vv = *(const float4*)(vsrc + cc * 4);
                *(float4*)&Vs[r * APAD + cc * 4] = vv;
            }
        }
        __syncthreads();

        float s[4][4];
        #pragma unroll
        for (int i = 0; i < 4; i++)
            #pragma unroll
            for (int j = 0; j < 4; j++) s[i][j] = 0.0f;

        #pragma unroll 8
        for (int d = 0; d < 64; d++) {
            float4 aq = *(const float4*)&Qt[d * APAD + ty * 4];
            float4 ak = *(const float4*)&Kt[d * APAD + tx * 4];
            float qa[4] = {aq.x, aq.y, aq.z, aq.w};
            float ka[4] = {ak.x, ak.y, ak.z, ak.w};
            #pragma unroll
            for (int i = 0; i < 4; i++)
                #pragma unroll
                for (int j = 0; j < 4; j++)
                    s[i][j] += qa[i] * ka[j];
        }

        #pragma unroll
        for (int i = 0; i < 4; i++) {
            const int q = q0 + ty * 4 + i;
            const long mrb = mbase + (long)q * SS + k0 + tx * 4;
            float sv[4];
            #pragma unroll
            for (int j = 0; j < 4; j++) {
                bool msk = mask_at(mask, mrb + j, mk);
                sv[j] = msk ? -1.0e9f : s[i][j] * 0.125f;
            }
            float mx = fmaxf(fmaxf(sv[0], sv[1]), fmaxf(sv[2], sv[3]));
            #pragma unroll
            for (int off = 1; off < 16; off <<= 1)
                mx = fmaxf(mx, __shfl_xor_sync(0xffffffffu, mx, off));
            const float mnew = fmaxf(mrow[i], mx);
            const float sc   = __expf(mrow[i] - mnew);
            float psum = 0.0f;
            #pragma unroll
            for (int j = 0; j < 4; j++) {
                float p = __expf(sv[j] - mnew);
                psum += p;
                Pt[(tx * 4 + j) * APAD + ty * 4 + i] = p;
            }
            #pragma unroll
            for (int off = 1; off < 16; off <<= 1)
                psum += __shfl_xor_sync(0xffffffffu, psum, off);
            lrow[i] = lrow[i] * sc + psum;
            mrow[i] = mnew;
            #pragma unroll
            for (int j = 0; j < 4; j++) o[i][j] *= sc;
        }
        __syncthreads();

        #pragma unroll 8
        for (int k = 0; k < 64; k++) {
            float4 ap = *(const float4*)&Pt[k * APAD + ty * 4];
            float4 av = *(const float4*)&Vs[k * APAD + tx * 4];
            float pa[4] = {ap.x, ap.y, ap.z, ap.w};
            float va[4] = {av.x, av.y, av.z, av.w};
            #pragma unroll
            for (int i = 0; i < 4; i++)
                #pragma unroll
                for (int j = 0; j < 4; j++)
                    o[i][j] += pa[i] * va[j];
        }
    }

    #pragma unroll
    for (int i = 0; i < 4; i++) {
        const float inv = 1.0f / lrow[i];
        float4 v;
        v.x = o[i][0] * inv; v.y = o[i][1] * inv;
        v.z = o[i][2] * inv; v.w = o[i][3] * inv;
        *(float4*)&Ob[(long)(row0 + q0 + ty * 4 + i) * SE + col0 + tx * 4] = v;
    }
}

// ---------------------------------------------------------------------------
// Launch
// ---------------------------------------------------------------------------
extern "C" void kernel_launch(void* const* d_in, const int* in_sizes, int n_in,
                              void* d_out, int out_size)
{
    const float* x    = (const float*)d_in[0];
    const void*  mask = d_in[1];
    const float* Wq   = (const float*)d_in[2];
    const float* bq   = (const float*)d_in[3];
    const float* Wk   = (const float*)d_in[4];
    const float* bk   = (const float*)d_in[5];
    const float* Wv   = (const float*)d_in[6];
    const float* bv   = (const float*)d_in[7];
    const float* Wo   = (const float*)d_in[8];
    const float* bo   = (const float*)d_in[9];
    float* out = (float*)d_out;

    float *Qb, *Kb, *Vb, *Ab;
    __nv_bfloat16 *xhi, *xlo, *ahi, *alo, *whi, *wlo;
    cudaGetSymbolAddress((void**)&Qb,  g_Q);
    cudaGetSymbolAddress((void**)&Kb,  g_K);
    cudaGetSymbolAddress((void**)&Vb,  g_V);
    cudaGetSymbolAddress((void**)&Ab,  g_A);
    cudaGetSymbolAddress((void**)&xhi, g_xhi);
    cudaGetSymbolAddress((void**)&xlo, g_xlo);
    cudaGetSymbolAddress((void**)&ahi, g_ahi);
    cudaGetSymbolAddress((void**)&alo, g_alo);
    cudaGetSymbolAddress((void**)&whi, g_whi);
    cudaGetSymbolAddress((void**)&wlo, g_wlo);

    cudaFuncSetAttribute(qkv_gemm_kernel,
                         cudaFuncAttributeMaxDynamicSharedMemorySize, GEMM_SMEM);
    cudaFuncSetAttribute(out_gemm_kernel,
                         cudaFuncAttributeMaxDynamicSharedMemorySize, GEMM_SMEM);
    cudaFuncSetAttribute(attn_kernel,
                         cudaFuncAttributeMaxDynamicSharedMemorySize, (int)ATT_SMEM);

    detect_mask_kind_kernel<<<1, 256>>>((const unsigned char*)mask);

    // Pre-split inputs to bf16 hi/lo
    const int nx = MTOT * SE;             // 4M
    const int nw = SE * SE;               // 1M
    split_kernel<<<nx / 1024, 256>>>(x,  xhi, xlo, nx);
    split_kernel<<<nw / 1024, 256>>>(Wq, whi + 0L * nw, wlo + 0L * nw, nw);
    split_kernel<<<nw / 1024, 256>>>(Wk, whi + 1L * nw, wlo + 1L * nw, nw);
    split_kernel<<<nw / 1024, 256>>>(Wv, whi + 2L * nw, wlo + 2L * nw, nw);
    split_kernel<<<nw / 1024, 256>>>(Wo, whi + 3L * nw, wlo + 3L * nw, nw);

    dim3 gqkv(SE / TN, MTOT / TM, 3);
    qkv_gemm_kernel<<<gqkv, 256, GEMM_SMEM>>>(bq, bk, bv);

    dim3 gat(SS / 64, SH, SB);
    attn_kernel<<<gat, 256, ATT_SMEM>>>(Qb, Kb, Vb, mask, Ab);

    split_kernel<<<nx / 1024, 256>>>(Ab, ahi, alo, nx);

    dim3 gout(SE / TN, MTOT / TM);
    out_gemm_kernel<<<gout, 256, GEMM_SMEM>>>(bo, out);
}

// round 4
// speedup vs baseline: 3.4079x; 2.5104x over previous
#include <cuda_runtime.h>
#include <cuda_bf16.h>
#include <cuda_fp16.h>
#include <stdint.h>

// Problem constants
#define SB   2
#define SS   2048
#define SE   1024
#define SH   16
#define SDK  64
#define MTOT (SB * SS)   // 4096

// Scratch (device globals: allocation-free rule)
__device__ __nv_bfloat16 g_xhi[MTOT * SE];
__device__ __nv_bfloat16 g_xlo[MTOT * SE];
__device__ __nv_bfloat16 g_ahi[MTOT * SE];
__device__ __nv_bfloat16 g_alo[MTOT * SE];
__device__ __nv_bfloat16 g_whi[4 * SE * SE];
__device__ __nv_bfloat16 g_wlo[4 * SE * SE];
__device__ __half g_q16[MTOT * SE];   // Q * 0.125, fp16
__device__ __half g_k16[MTOT * SE];   // K fp16
__device__ __half g_vhi[MTOT * SE];   // V fp16 hi
__device__ __half g_vlo[MTOT * SE];   // V fp16 lo
__device__ uint32_t g_mb[SB * SS * SS / 32];   // packed mask bits
__device__ int   g_mask_kind;   // 0 = u8, 1 = i32, 2 = f32

// ---------------------------------------------------------------------------
// Helpers
// ---------------------------------------------------------------------------
__device__ __forceinline__ uint32_t smem_u32(const void* p) {
    uint32_t a;
    asm("{ .reg .u64 t; cvta.to.shared.u64 t, %1; cvt.u32.u64 %0, t; }"
        : "=r"(a) : "l"(p));
    return a;
}

__device__ __forceinline__ void cp_async16(uint32_t dst, const void* src) {
    asm volatile("cp.async.cg.shared.global [%0], [%1], 16;"
                 :: "r"(dst), "l"(src) : "memory");
}
__device__ __forceinline__ void cp_commit() {
    asm volatile("cp.async.commit_group;" ::: "memory");
}
template <int N>
__device__ __forceinline__ void cp_wait() {
    asm volatile("cp.async.wait_group %0;" :: "n"(N) : "memory");
}

__device__ __forceinline__ void ldm_x4(uint32_t* r, uint32_t addr) {
    asm volatile("ldmatrix.sync.aligned.m8n8.x4.shared.b16 {%0,%1,%2,%3}, [%4];"
                 : "=r"(r[0]), "=r"(r[1]), "=r"(r[2]), "=r"(r[3]) : "r"(addr));
}
__device__ __forceinline__ void ldm_x4_t(uint32_t* r, uint32_t addr) {
    asm volatile("ldmatrix.sync.aligned.m8n8.x4.trans.shared.b16 {%0,%1,%2,%3}, [%4];"
                 : "=r"(r[0]), "=r"(r[1]), "=r"(r[2]), "=r"(r[3]) : "r"(addr));
}

__device__ __forceinline__ void mma_bf16(float* d, const uint32_t* a,
                                         uint32_t b0, uint32_t b1) {
    asm volatile(
        "mma.sync.aligned.m16n8k16.row.col.f32.bf16.bf16.f32 "
        "{%0,%1,%2,%3}, {%4,%5,%6,%7}, {%8,%9}, {%0,%1,%2,%3};"
        : "+f"(d[0]), "+f"(d[1]), "+f"(d[2]), "+f"(d[3])
        : "r"(a[0]), "r"(a[1]), "r"(a[2]), "r"(a[3]), "r"(b0), "r"(b1));
}
__device__ __forceinline__ void mma_fp16(float* d, const uint32_t* a,
                                         uint32_t b0, uint32_t b1) {
    asm volatile(
        "mma.sync.aligned.m16n8k16.row.col.f32.f16.f16.f32 "
        "{%0,%1,%2,%3}, {%4,%5,%6,%7}, {%8,%9}, {%0,%1,%2,%3};"
        : "+f"(d[0]), "+f"(d[1]), "+f"(d[2]), "+f"(d[3])
        : "r"(a[0]), "r"(a[1]), "r"(a[2]), "r"(a[3]), "r"(b0), "r"(b1));
}

__device__ __forceinline__ uint32_t packh2(float a, float b) {
    __half2 h = __floats2half2_rn(a, b);
    return *reinterpret_cast<uint32_t*>(&h);
}

// ---------------------------------------------------------------------------
// Mask dtype detection + bit packing
// ---------------------------------------------------------------------------
__global__ void detect_mask_kind_kernel(const unsigned char* __restrict__ m) {
    __shared__ int s1, s3f;
    if (threadIdx.x == 0) { s1 = 0; s3f = 0; }
    __syncthreads();
    int n1 = 0, n3f = 0;
    for (int i = threadIdx.x * 4; i < 65536; i += 256 * 4) {
        n1  += (m[i + 1] != 0);
        n3f += (m[i + 3] == 0x3F);
    }
    atomicAdd(&s1, n1);
    atomicAdd(&s3f, n3f);
    __syncthreads();
    if (threadIdx.x == 0) {
        int kind = 0;
        if (s1 == 0) kind = (s3f > 0) ? 2 : 1;
        g_mask_kind = kind;
    }
}

__device__ __forceinline__ bool mask_at(const void* m, long idx, int kind) {
    if (kind == 0) return ((const unsigned char*)m)[idx] != 0;
    if (kind == 1) return ((const int*)m)[idx] != 0;
    return ((const float*)m)[idx] != 0.0f;
}

__global__ void pack_mask_kernel(const void* __restrict__ m) {
    const long t = (long)blockIdx.x * 256 + threadIdx.x;   // bit index
    const int kind = g_mask_kind;
    bool v = mask_at(m, t, kind);
    uint32_t w = __ballot_sync(0xffffffffu, v);
    if ((threadIdx.x & 31) == 0) g_mb[t >> 5] = w;
}

// ---------------------------------------------------------------------------
// fp32 -> bf16 hi/lo split
// ---------------------------------------------------------------------------
__global__ void split_kernel(const float* __restrict__ src,
                             __nv_bfloat16* __restrict__ hi,
                             __nv_bfloat16* __restrict__ lo, int n) {
    int i = (blockIdx.x * blockDim.x + threadIdx.x) * 4;
    if (i >= n) return;
    float4 v = *(const float4*)(src + i);
    __nv_bfloat16 h0 = __float2bfloat16_rn(v.x);
    __nv_bfloat16 h1 = __float2bfloat16_rn(v.y);
    __nv_bfloat16 h2 = __float2bfloat16_rn(v.z);
    __nv_bfloat16 h3 = __float2bfloat16_rn(v.w);
    __nv_bfloat162 hA, hB, lA, lB;
    hA.x = h0; hA.y = h1; hB.x = h2; hB.y = h3;
    lA.x = __float2bfloat16_rn(v.x - __bfloat162float(h0));
    lA.y = __float2bfloat16_rn(v.y - __bfloat162float(h1));
    lB.x = __float2bfloat16_rn(v.z - __bfloat162float(h2));
    lB.y = __float2bfloat16_rn(v.w - __bfloat162float(h3));
    *(__nv_bfloat162*)(hi + i)     = hA;
    *(__nv_bfloat162*)(hi + i + 2) = hB;
    *(__nv_bfloat162*)(lo + i)     = lA;
    *(__nv_bfloat162*)(lo + i + 2) = lB;
}

// ---------------------------------------------------------------------------
// bf16 3-pass MMA GEMM:  C = A @ W^T + bias, with mode-dependent epilogue.
// mode 0: fp32 -> Cf       (final output)
// mode 1: fp16((v)*0.125) -> Ch0   (Q)
// mode 2: fp16(v) -> Ch0           (K)
// mode 3: fp16 hi -> Ch0, fp16 lo -> Ch1   (V)
// ---------------------------------------------------------------------------
#define TM 128
#define TN 128
#define KC 32
#define NC (SE / KC)
#define BUFB  8192
#define STAGEB (4 * BUFB)
#define GEMM_SMEM (2 * STAGEB)    // 65536

__device__ __forceinline__ uint32_t sw_addr(uint32_t base, int r, int c16) {
    return base + r * 64 + ((c16 ^ ((r >> 1) & 3)) << 4);
}

__device__ __forceinline__ void mma_gemm_body(
    const __nv_bfloat16* __restrict__ Ahi, const __nv_bfloat16* __restrict__ Alo,
    const __nv_bfloat16* __restrict__ Whi, const __nv_bfloat16* __restrict__ Wlo,
    const float* __restrict__ bias, int mode,
    float* __restrict__ Cf, __half* __restrict__ Ch0, __half* __restrict__ Ch1)
{
    extern __shared__ char dynsm[];
    const uint32_t sb = smem_u32(dynsm);
    const int tid  = threadIdx.x;
    const int lane = tid & 31;
    const int wid  = tid >> 5;
    const int wm   = (wid >> 2) * 64;
    const int wn   = (wid & 3) * 32;
    const int bm   = blockIdx.y * TM;
    const int bn   = blockIdx.x * TN;

    const __nv_bfloat16* srcA[2] = { Ahi + (long)bm * SE, Alo + (long)bm * SE };
    const __nv_bfloat16* srcB[2] = { Whi + (long)bn * SE, Wlo + (long)bn * SE };

    float acc[4][4][4];
    #pragma unroll
    for (int i = 0; i < 4; i++)
        #pragma unroll
        for (int j = 0; j < 4; j++)
            #pragma unroll
            for (int k = 0; k < 4; k++) acc[i][j][k] = 0.0f;

    auto issue = [&](int chunk, int buf) {
        const int kc0 = chunk * KC;
        #pragma unroll
        for (int q = 0; q < 8; q++) {
            const int mat    = q >> 1;
            const int within = (q & 1) * 256 + tid;
            const int r   = within >> 2;
            const int c16 = within & 3;
            const __nv_bfloat16* s =
                (mat < 2 ? srcA[mat] : srcB[mat - 2]) + (long)r * SE + kc0 + c16 * 8;
            cp_async16(sw_addr(sb + buf * STAGEB + mat * BUFB, r, c16), s);
        }
        cp_commit();
    };

    issue(0, 0);

    for (int it = 0; it < NC; ++it) {
        const int buf = it & 1;
        if (it + 1 < NC) { issue(it + 1, buf ^ 1); cp_wait<1>(); }
        else             { cp_wait<0>(); }
        __syncthreads();

        const uint32_t AH = sb + buf * STAGEB;
        const uint32_t AL = AH + BUFB;
        const uint32_t BH = AH + 2 * BUFB;
        const uint32_t BL = AH + 3 * BUFB;

        #pragma unroll
        for (int ks = 0; ks < 2; ks++) {
            uint32_t ah[4][4], al[4][4], bh[2][4], bl[2][4];
            const int ar   = (lane & 15);
            const int ac16 = ks * 2 + (lane >> 4);
            #pragma unroll
            for (int i = 0; i < 4; i++) {
                const int r = wm + i * 16 + ar;
                ldm_x4(ah[i], sw_addr(AH, r, ac16));
                ldm_x4(al[i], sw_addr(AL, r, ac16));
            }
            const int br   = ((lane >> 4) << 3) + (lane & 7);
            const int bc16 = ks * 2 + ((lane >> 3) & 1);
            #pragma unroll
            for (int p = 0; p < 2; p++) {
                const int r = wn + p * 16 + br;
                ldm_x4(bh[p], sw_addr(BH, r, bc16));
                ldm_x4(bl[p], sw_addr(BL, r, bc16));
            }
            #pragma unroll
            for (int i = 0; i < 4; i++)
                #pragma unroll
                for (int j = 0; j < 4; j++) {
                    const int p = j >> 1, o = (j & 1) * 2;
                    mma_bf16(acc[i][j], ah[i], bh[p][o], bh[p][o + 1]);
                    mma_bf16(acc[i][j], ah[i], bl[p][o], bl[p][o + 1]);
                    mma_bf16(acc[i][j], al[i], bh[p][o], bh[p][o + 1]);
                }
        }
        __syncthreads();
    }

    #pragma unroll
    for (int j = 0; j < 4; j++) {
        const int gn = bn + wn + j * 8 + ((lane & 3) << 1);
        const float b0 = bias[gn], b1 = bias[gn + 1];
        #pragma unroll
        for (int i = 0; i < 4; i++) {
            const int gm = bm + wm + i * 16 + (lane >> 2);
            float v0 = acc[i][j][0] + b0, v1 = acc[i][j][1] + b1;
            float v2 = acc[i][j][2] + b0, v3 = acc[i][j][3] + b1;
            if (mode == 0) {
                float2 p0 = {v0, v1}, p1 = {v2, v3};
                *(float2*)(Cf + (long)gm * SE + gn)       = p0;
                *(float2*)(Cf + (long)(gm + 8) * SE + gn) = p1;
            } else if (mode == 1) {
                __half2 h0 = __floats2half2_rn(v0 * 0.125f, v1 * 0.125f);
                __half2 h1 = __floats2half2_rn(v2 * 0.125f, v3 * 0.125f);
                *(__half2*)(Ch0 + (long)gm * SE + gn)       = h0;
                *(__half2*)(Ch0 + (long)(gm + 8) * SE + gn) = h1;
            } else if (mode == 2) {
                __half2 h0 = __floats2half2_rn(v0, v1);
                __half2 h1 = __floats2half2_rn(v2, v3);
                *(__half2*)(Ch0 + (long)gm * SE + gn)       = h0;
                *(__half2*)(Ch0 + (long)(gm + 8) * SE + gn) = h1;
            } else {
                __half h0 = __float2half_rn(v0), h1 = __float2half_rn(v1);
                __half h2 = __float2half_rn(v2), h3 = __float2half_rn(v3);
                __half2 hh0 = {h0, h1}, hh1 = {h2, h3};
                __half2 ll0 = {__float2half_rn(v0 - __half2float(h0)),
                               __float2half_rn(v1 - __half2float(h1))};
                __half2 ll1 = {__float2half_rn(v2 - __half2float(h2)),
                               __float2half_rn(v3 - __half2float(h3))};
                *(__half2*)(Ch0 + (long)gm * SE + gn)       = hh0;
                *(__half2*)(Ch0 + (long)(gm + 8) * SE + gn) = hh1;
                *(__half2*)(Ch1 + (long)gm * SE + gn)       = ll0;
                *(__half2*)(Ch1 + (long)(gm + 8) * SE + gn) = ll1;
            }
        }
    }
}

__global__ __launch_bounds__(256, 1)
void qkv_gemm_kernel(const float* __restrict__ bq, const float* __restrict__ bk,
                     const float* __restrict__ bv)
{
    const int z = blockIdx.z;
    const float* bias = (z == 0) ? bq : (z == 1) ? bk : bv;
    const int mode = (z == 0) ? 1 : (z == 1) ? 2 : 3;
    __half* c0 = (z == 0) ? g_q16 : (z == 1) ? g_k16 : g_vhi;
    mma_gemm_body(g_xhi, g_xlo,
                  g_whi + (long)z * SE * SE, g_wlo + (long)z * SE * SE,
                  bias, mode, nullptr, c0, g_vlo);
}

__global__ __launch_bounds__(256, 1)
void out_gemm_kernel(const float* __restrict__ bo, float* __restrict__ out)
{
    mma_gemm_body(g_ahi, g_alo,
                  g_whi + 3L * SE * SE, g_wlo + 3L * SE * SE,
                  bo, 0, out, nullptr, nullptr);
}

// ---------------------------------------------------------------------------
// Tensor-core flash attention.
// CTA: 128 q rows x one (b,h). 8 warps, warp = 16 q rows. k-tile 64.
// QK^T: fp16 1-pass (Q prescaled by 1/8). PV: P fp16 1x, V hi+lo (2 passes).
// Mask via packed bitset. Online softmax in registers.
// SMEM: Q 16KB + 2 stages x (K 8KB + Vh 8KB + Vl 8KB) = 64KB.
// ---------------------------------------------------------------------------
#define AT_NT (SS / 64)
#define AT_SMEM 65536
#define QS_OFF 0
#define STG_OFF(s) (16384 + (s) * 24576)

__device__ __forceinline__ uint32_t asw(uint32_t base, int r, int c) {
    return base + r * 128 + ((c ^ (r & 7)) << 4);
}

__global__ __launch_bounds__(256, 2)
void attn_kernel(const __half* __restrict__ Qg, const __half* __restrict__ Kg,
                 const __half* __restrict__ Vh, const __half* __restrict__ Vl,
                 __nv_bfloat16* __restrict__ Ahi, __nv_bfloat16* __restrict__ Alo)
{
    extern __shared__ char dynsm[];
    const uint32_t sb = smem_u32(dynsm);
    const int tid  = threadIdx.x;
    const int lane = tid & 31;
    const int wid  = tid >> 5;
    const int q0   = blockIdx.x * 128;
    const int h    = blockIdx.y;
    const int b    = blockIdx.z;
    const int row0 = b * SS;
    const int col0 = h * SDK;
    const int wq0  = wid * 16;

    const unsigned long long* mb64 =
        reinterpret_cast<const unsigned long long*>(g_mb);
    const long mrow0 = ((long)(b * SS + q0 + wq0 + (lane >> 2))) * 32;

    // Q tile load (once)
    {
        #pragma unroll
        for (int m = 0; m < 4; m++) {
            const int idx = m * 256 + tid;      // 0..1023
            const int r = idx >> 3, c = idx & 7;
            cp_async16(asw(sb + QS_OFF, r, c),
                       Qg + (long)(row0 + q0 + r) * SE + col0 + c * 8);
        }
    }
    auto issue_kv = [&](int kt, int s) {
        const int k0 = kt * 64;
        const __half* srcs[3] = { Kg, Vh, Vl };
        #pragma unroll
        for (int m = 0; m < 6; m++) {
            const int idx = m * 256 + tid;      // 0..1535
            const int mat = idx >> 9;
            const int wi  = idx & 511;
            const int r = wi >> 3, c = wi & 7;
            cp_async16(asw(sb + STG_OFF(s) + mat * 8192, r, c),
                       srcs[mat] + (long)(row0 + k0 + r) * SE + col0 + c * 8);
        }
    };
    issue_kv(0, 0);
    cp_commit();

    uint32_t qf[4][4];
    float oacc[8][4];
    float mrow[2] = {-3.0e38f, -3.0e38f};
    float lrow[2] = {0.0f, 0.0f};
    #pragma unroll
    for (int d = 0; d < 8; d++)
        #pragma unroll
        for (int k = 0; k < 4; k++) oacc[d][k] = 0.0f;

    for (int it = 0; it < AT_NT; ++it) {
        const int buf = it & 1;
        if (it + 1 < AT_NT) { issue_kv(it + 1, buf ^ 1); cp_commit(); cp_wait<1>(); }
        else                { cp_wait<0>(); }
        __syncthreads();

        if (it == 0) {
            #pragma unroll
            for (int ks = 0; ks < 4; ks++)
                ldm_x4(qf[ks], asw(sb + QS_OFF, wq0 + (lane & 15),
                                   ks * 2 + (lane >> 4)));
        }

        const uint32_t Kb  = sb + STG_OFF(buf);
        const uint32_t Vhb = Kb + 8192;
        const uint32_t Vlb = Kb + 16384;

        // S = Q @ K^T (scaled)
        float sacc[8][4];
        #pragma unroll
        for (int nb = 0; nb < 8; nb++)
            #pragma unroll
            for (int k = 0; k < 4; k++) sacc[nb][k] = 0.0f;

        #pragma unroll
        for (int ks = 0; ks < 4; ks++) {
            uint32_t kf[4][4];
            const int br  = ((lane >> 4) << 3) + (lane & 7);
            const int bc  = ks * 2 + ((lane >> 3) & 1);
            #pragma unroll
            for (int p = 0; p < 4; p++)
                ldm_x4(kf[p], asw(Kb, p * 16 + br, bc));
            #pragma unroll
            for (int nb = 0; nb < 8; nb++)
                mma_fp16(sacc[nb], qf[ks], kf[nb >> 1][(nb & 1) * 2],
                         kf[nb >> 1][(nb & 1) * 2 + 1]);
        }

        // mask + online softmax
        unsigned long long mw0 = mb64[mrow0 + it];
        unsigned long long mw1 = mb64[mrow0 + 256 + it];
        #pragma unroll
        for (int i = 0; i < 2; i++) {
            const unsigned long long mw = i ? mw1 : mw0;
            float mx = -3.0e38f;
            #pragma unroll
            for (int nb = 0; nb < 8; nb++) {
                #pragma unroll
                for (int e = 0; e < 2; e++) {
                    const int bit = nb * 8 + ((lane & 3) << 1) + e;
                    float s = sacc[nb][2 * i + e];
                    s = ((mw >> bit) & 1ull) ? -1.0e9f : s;
                    sacc[nb][2 * i + e] = s;
                    mx = fmaxf(mx, s);
                }
            }
            mx = fmaxf(mx, __shfl_xor_sync(0xffffffffu, mx, 1));
            mx = fmaxf(mx, __shfl_xor_sync(0xffffffffu, mx, 2));
            const float mnew = fmaxf(mrow[i], mx);
            const float sc   = __expf(mrow[i] - mnew);
            mrow[i] = mnew;
            float sum = 0.0f;
            #pragma unroll
            for (int nb = 0; nb < 8; nb++) {
                #pragma unroll
                for (int e = 0; e < 2; e++) {
                    float p = __expf(sacc[nb][2 * i + e] - mnew);
                    sacc[nb][2 * i + e] = p;
                    sum += p;
                }
            }
            sum += __shfl_xor_sync(0xffffffffu, sum, 1);
            sum += __shfl_xor_sync(0xffffffffu, sum, 2);
            lrow[i] = lrow[i] * sc + sum;
            #pragma unroll
            for (int d = 0; d < 8; d++) {
                oacc[d][2 * i]     *= sc;
                oacc[d][2 * i + 1] *= sc;
            }
        }

        // P fp16 a-frags
        uint32_t pf[4][4];
        #pragma unroll
        for (int kk = 0; kk < 4; kk++) {
            pf[kk][0] = packh2(sacc[2 * kk][0],     sacc[2 * kk][1]);
            pf[kk][1] = packh2(sacc[2 * kk][2],     sacc[2 * kk][3]);
            pf[kk][2] = packh2(sacc[2 * kk + 1][0], sacc[2 * kk + 1][1]);
            pf[kk][3] = packh2(sacc[2 * kk + 1][2], sacc[2 * kk + 1][3]);
        }

        // O += P @ V (hi + lo)
        #pragma unroll
        for (int kk = 0; kk < 4; kk++) {
            const int vr = kk * 16 + (lane & 15);
            #pragma unroll
            for (int dp = 0; dp < 4; dp++) {
                const int vc = dp * 2 + (lane >> 4);
                uint32_t vf[4];
                ldm_x4_t(vf, asw(Vhb, vr, vc));
                mma_fp16(oacc[2 * dp],     pf[kk], vf[0], vf[1]);
                mma_fp16(oacc[2 * dp + 1], pf[kk], vf[2], vf[3]);
                ldm_x4_t(vf, asw(Vlb, vr, vc));
                mma_fp16(oacc[2 * dp],     pf[kk], vf[0], vf[1]);
                mma_fp16(oacc[2 * dp + 1], pf[kk], vf[2], vf[3]);
            }
        }
        __syncthreads();
    }

    // epilogue: normalize, split to bf16 hi/lo
    #pragma unroll
    for (int i = 0; i < 2; i++) {
        const float inv = 1.0f / lrow[i];
        const long gq = row0 + q0 + wq0 + (lane >> 2) + 8 * i;
        #pragma unroll
        for (int d = 0; d < 8; d++) {
            const int gc = col0 + d * 8 + ((lane & 3) << 1);
            float o0 = oacc[d][2 * i] * inv, o1 = oacc[d][2 * i + 1] * inv;
            __nv_bfloat16 h0 = __float2bfloat16_rn(o0);
            __nv_bfloat16 h1 = __float2bfloat16_rn(o1);
            __nv_bfloat162 hh = {h0, h1};
            __nv_bfloat162 ll = {__float2bfloat16_rn(o0 - __bfloat162float(h0)),
                                 __float2bfloat16_rn(o1 - __bfloat162float(h1))};
            *(__nv_bfloat162*)(Ahi + gq * SE + gc) = hh;
            *(__nv_bfloat162*)(Alo + gq * SE + gc) = ll;
        }
    }
}

// ---------------------------------------------------------------------------
// Launch
// ---------------------------------------------------------------------------
extern "C" void kernel_launch(void* const* d_in, const int* in_sizes, int n_in,
                              void* d_out, int out_size)
{
    const float* x    = (const float*)d_in[0];
    const void*  mask = d_in[1];
    const float* Wq   = (const float*)d_in[2];
    const float* bq   = (const float*)d_in[3];
    const float* Wk   = (const float*)d_in[4];
    const float* bk   = (const float*)d_in[5];
    const float* Wv   = (const float*)d_in[6];
    const float* bv   = (const float*)d_in[7];
    const float* Wo   = (const float*)d_in[8];
    const float* bo   = (const float*)d_in[9];
    float* out = (float*)d_out;

    __nv_bfloat16 *xhi, *xlo, *ahi, *alo, *whi, *wlo;
    __half *q16, *k16, *vhi, *vlo;
    cudaGetSymbolAddress((void**)&xhi, g_xhi);
    cudaGetSymbolAddress((void**)&xlo, g_xlo);
    cudaGetSymbolAddress((void**)&ahi, g_ahi);
    cudaGetSymbolAddress((void**)&alo, g_alo);
    cudaGetSymbolAddress((void**)&whi, g_whi);
    cudaGetSymbolAddress((void**)&wlo, g_wlo);
    cudaGetSymbolAddress((void**)&q16, g_q16);
    cudaGetSymbolAddress((void**)&k16, g_k16);
    cudaGetSymbolAddress((void**)&vhi, g_vhi);
    cudaGetSymbolAddress((void**)&vlo, g_vlo);

    cudaFuncSetAttribute(qkv_gemm_kernel,
                         cudaFuncAttributeMaxDynamicSharedMemorySize, GEMM_SMEM);
    cudaFuncSetAttribute(out_gemm_kernel,
                         cudaFuncAttributeMaxDynamicSharedMemorySize, GEMM_SMEM);
    cudaFuncSetAttribute(attn_kernel,
                         cudaFuncAttributeMaxDynamicSharedMemorySize, AT_SMEM);

    detect_mask_kind_kernel<<<1, 256>>>((const unsigned char*)mask);
    pack_mask_kernel<<<SB * SS * SS / 256, 256>>>(mask);

    const int nx = MTOT * SE;
    const int nw = SE * SE;
    split_kernel<<<nx / 1024, 256>>>(x,  xhi, xlo, nx);
    split_kernel<<<nw / 1024, 256>>>(Wq, whi + 0L * nw, wlo + 0L * nw, nw);
    split_kernel<<<nw / 1024, 256>>>(Wk, whi + 1L * nw, wlo + 1L * nw, nw);
    split_kernel<<<nw / 1024, 256>>>(Wv, whi + 2L * nw, wlo + 2L * nw, nw);
    split_kernel<<<nw / 1024, 256>>>(Wo, whi + 3L * nw, wlo + 3L * nw, nw);

    dim3 gqkv(SE / TN, MTOT / TM, 3);
    qkv_gemm_kernel<<<gqkv, 256, GEMM_SMEM>>>(bq, bk, bv);

    dim3 gat(SS / 128, SH, SB);
    attn_kernel<<<gat, 256, AT_SMEM>>>(q16, k16, vhi, vlo, ahi, alo);

    dim3 gout(SE / TN, MTOT / TM);
    out_gemm_kernel<<<gout, 256, GEMM_SMEM>>>(bo, out);
}

// round 5
// speedup vs baseline: 5.4807x; 1.6082x over previous
#include <cuda_runtime.h>
#include <cuda_bf16.h>
#include <cuda_fp16.h>
#include <stdint.h>

// Problem constants
#define SB   2
#define SS   2048
#define SE   1024
#define SH   16
#define SDK  64
#define MTOT (SB * SS)   // 4096

// Scratch (device globals: allocation-free rule)
__device__ __half g_x16[MTOT * SE];
__device__ __half g_a16[MTOT * SE];
__device__ __half g_w16[4 * SE * SE];
__device__ __half g_q16[MTOT * SE];   // Q * 0.125, fp16
__device__ __half g_k16[MTOT * SE];   // K fp16
__device__ __half g_vhi[MTOT * SE];   // V fp16 hi
__device__ __half g_vlo[MTOT * SE];   // V fp16 lo
__device__ uint32_t g_mb[SB * SS * SS / 32];   // packed mask bits
__device__ int   g_mask_kind;   // 0 = u8, 1 = i32, 2 = f32

// ---------------------------------------------------------------------------
// Helpers
// ---------------------------------------------------------------------------
__device__ __forceinline__ uint32_t smem_u32(const void* p) {
    uint32_t a;
    asm("{ .reg .u64 t; cvta.to.shared.u64 t, %1; cvt.u32.u64 %0, t; }"
        : "=r"(a) : "l"(p));
    return a;
}

__device__ __forceinline__ void cp_async16(uint32_t dst, const void* src) {
    asm volatile("cp.async.cg.shared.global [%0], [%1], 16;"
                 :: "r"(dst), "l"(src) : "memory");
}
__device__ __forceinline__ void cp_commit() {
    asm volatile("cp.async.commit_group;" ::: "memory");
}
template <int N>
__device__ __forceinline__ void cp_wait() {
    asm volatile("cp.async.wait_group %0;" :: "n"(N) : "memory");
}

__device__ __forceinline__ void ldm_x4(uint32_t* r, uint32_t addr) {
    asm volatile("ldmatrix.sync.aligned.m8n8.x4.shared.b16 {%0,%1,%2,%3}, [%4];"
                 : "=r"(r[0]), "=r"(r[1]), "=r"(r[2]), "=r"(r[3]) : "r"(addr));
}
__device__ __forceinline__ void ldm_x4_t(uint32_t* r, uint32_t addr) {
    asm volatile("ldmatrix.sync.aligned.m8n8.x4.trans.shared.b16 {%0,%1,%2,%3}, [%4];"
                 : "=r"(r[0]), "=r"(r[1]), "=r"(r[2]), "=r"(r[3]) : "r"(addr));
}

__device__ __forceinline__ void mma_fp16(float* d, const uint32_t* a,
                                         uint32_t b0, uint32_t b1) {
    asm volatile(
        "mma.sync.aligned.m16n8k16.row.col.f32.f16.f16.f32 "
        "{%0,%1,%2,%3}, {%4,%5,%6,%7}, {%8,%9}, {%0,%1,%2,%3};"
        : "+f"(d[0]), "+f"(d[1]), "+f"(d[2]), "+f"(d[3])
        : "r"(a[0]), "r"(a[1]), "r"(a[2]), "r"(a[3]), "r"(b0), "r"(b1));
}

__device__ __forceinline__ uint32_t packh2(float a, float b) {
    __half2 h = __floats2half2_rn(a, b);
    return *reinterpret_cast<uint32_t*>(&h);
}

// shared 128B-row swizzle: 16B chunk c (0..7), row r
__device__ __forceinline__ uint32_t asw(uint32_t base, int r, int c) {
    return base + r * 128 + ((c ^ (r & 7)) << 4);
}

// ---------------------------------------------------------------------------
// Mask dtype detection + bit packing
// ---------------------------------------------------------------------------
__global__ void detect_mask_kind_kernel(const unsigned char* __restrict__ m) {
    __shared__ int s1, s3f;
    if (threadIdx.x == 0) { s1 = 0; s3f = 0; }
    __syncthreads();
    int n1 = 0, n3f = 0;
    for (int i = threadIdx.x * 4; i < 65536; i += 256 * 4) {
        n1  += (m[i + 1] != 0);
        n3f += (m[i + 3] == 0x3F);
    }
    atomicAdd(&s1, n1);
    atomicAdd(&s3f, n3f);
    __syncthreads();
    if (threadIdx.x == 0) {
        int kind = 0;
        if (s1 == 0) kind = (s3f > 0) ? 2 : 1;
        g_mask_kind = kind;
    }
}

__device__ __forceinline__ bool mask_at(const void* m, long idx, int kind) {
    if (kind == 0) return ((const unsigned char*)m)[idx] != 0;
    if (kind == 1) return ((const int*)m)[idx] != 0;
    return ((const float*)m)[idx] != 0.0f;
}

__global__ void pack_mask_kernel(const void* __restrict__ m) {
    const long t = (long)blockIdx.x * 256 + threadIdx.x;   // bit index
    const int kind = g_mask_kind;
    bool v = mask_at(m, t, kind);
    uint32_t w = __ballot_sync(0xffffffffu, v);
    if ((threadIdx.x & 31) == 0) g_mb[t >> 5] = w;
}

// ---------------------------------------------------------------------------
// fp32 -> fp16 convert
// ---------------------------------------------------------------------------
__global__ void tohalf_kernel(const float* __restrict__ src,
                              __half* __restrict__ dst, int n) {
    int i = (blockIdx.x * blockDim.x + threadIdx.x) * 4;
    if (i >= n) return;
    float4 v = *(const float4*)(src + i);
    __half2 a = __floats2half2_rn(v.x, v.y);
    __half2 b = __floats2half2_rn(v.z, v.w);
    *(__half2*)(dst + i)     = a;
    *(__half2*)(dst + i + 2) = b;
}

// ---------------------------------------------------------------------------
// Single-pass fp16 MMA GEMM:  C = A @ W^T + bias, mode-dependent epilogue.
// mode 0: fp32 -> Cf            (final output)
// mode 1: fp16(v*0.125) -> Ch0  (Q)
// mode 2: fp16(v) -> Ch0        (K)
// mode 3: fp16 hi -> Ch0, fp16 lo -> Ch1   (V)
// Block tile 128x128, K-chunk 64, 8 warps (warp tile 64x32), 2-stage cp.async.
// ---------------------------------------------------------------------------
#define TM 128
#define TN 128
#define KC 64
#define NC (SE / KC)              // 16
#define BUFB  16384               // 128 rows x 128B
#define STAGEB (2 * BUFB)         // A, B
#define GEMM_SMEM (2 * STAGEB)    // 65536

__device__ __forceinline__ void mma_gemm_body(
    const __half* __restrict__ Ag, const __half* __restrict__ Wg,
    const float* __restrict__ bias, int mode,
    float* __restrict__ Cf, __half* __restrict__ Ch0, __half* __restrict__ Ch1)
{
    extern __shared__ char dynsm[];
    const uint32_t sb = smem_u32(dynsm);
    const int tid  = threadIdx.x;
    const int lane = tid & 31;
    const int wid  = tid >> 5;
    const int wm   = (wid >> 2) * 64;
    const int wn   = (wid & 3) * 32;
    const int bm   = blockIdx.y * TM;
    const int bn   = blockIdx.x * TN;

    const __half* srcA = Ag + (long)bm * SE;
    const __half* srcB = Wg + (long)bn * SE;

    float acc[4][4][4];
    #pragma unroll
    for (int i = 0; i < 4; i++)
        #pragma unroll
        for (int j = 0; j < 4; j++)
            #pragma unroll
            for (int k = 0; k < 4; k++) acc[i][j][k] = 0.0f;

    auto issue = [&](int chunk, int buf) {
        const int kc0 = chunk * KC;
        #pragma unroll
        for (int q = 0; q < 8; q++) {
            const int mat    = q >> 2;               // 0:A 1:B
            const int within = (q & 3) * 256 + tid;  // 0..1023
            const int r = within >> 3, c = within & 7;
            const __half* s = (mat ? srcB : srcA) + (long)r * SE + kc0 + c * 8;
            cp_async16(asw(sb + buf * STAGEB + mat * BUFB, r, c), s);
        }
        cp_commit();
    };

    issue(0, 0);

    for (int it = 0; it < NC; ++it) {
        const int buf = it & 1;
        if (it + 1 < NC) { issue(it + 1, buf ^ 1); cp_wait<1>(); }
        else             { cp_wait<0>(); }
        __syncthreads();

        const uint32_t Ab = sb + buf * STAGEB;
        const uint32_t Bb = Ab + BUFB;

        #pragma unroll
        for (int ks = 0; ks < 4; ks++) {
            uint32_t af[4][4], bf[2][4];
            const int ar = (lane & 15);
            const int ac = ks * 2 + (lane >> 4);
            #pragma unroll
            for (int i = 0; i < 4; i++)
                ldm_x4(af[i], asw(Ab, wm + i * 16 + ar, ac));
            const int br = ((lane >> 4) << 3) + (lane & 7);
            const int bc = ks * 2 + ((lane >> 3) & 1);
            #pragma unroll
            for (int p = 0; p < 2; p++)
                ldm_x4(bf[p], asw(Bb, wn + p * 16 + br, bc));
            #pragma unroll
            for (int i = 0; i < 4; i++)
                #pragma unroll
                for (int j = 0; j < 4; j++)
                    mma_fp16(acc[i][j], af[i], bf[j >> 1][(j & 1) * 2],
                             bf[j >> 1][(j & 1) * 2 + 1]);
        }
        __syncthreads();
    }

    #pragma unroll
    for (int j = 0; j < 4; j++) {
        const int gn = bn + wn + j * 8 + ((lane & 3) << 1);
        const float b0 = bias[gn], b1 = bias[gn + 1];
        #pragma unroll
        for (int i = 0; i < 4; i++) {
            const int gm = bm + wm + i * 16 + (lane >> 2);
            float v0 = acc[i][j][0] + b0, v1 = acc[i][j][1] + b1;
            float v2 = acc[i][j][2] + b0, v3 = acc[i][j][3] + b1;
            if (mode == 0) {
                float2 p0 = {v0, v1}, p1 = {v2, v3};
                *(float2*)(Cf + (long)gm * SE + gn)       = p0;
                *(float2*)(Cf + (long)(gm + 8) * SE + gn) = p1;
            } else if (mode == 1) {
                *(__half2*)(Ch0 + (long)gm * SE + gn) =
                    __floats2half2_rn(v0 * 0.125f, v1 * 0.125f);
                *(__half2*)(Ch0 + (long)(gm + 8) * SE + gn) =
                    __floats2half2_rn(v2 * 0.125f, v3 * 0.125f);
            } else if (mode == 2) {
                *(__half2*)(Ch0 + (long)gm * SE + gn) = __floats2half2_rn(v0, v1);
                *(__half2*)(Ch0 + (long)(gm + 8) * SE + gn) = __floats2half2_rn(v2, v3);
            } else {
                __half h0 = __float2half_rn(v0), h1 = __float2half_rn(v1);
                __half h2 = __float2half_rn(v2), h3 = __float2half_rn(v3);
                __half2 hh0 = {h0, h1}, hh1 = {h2, h3};
                __half2 ll0 = {__float2half_rn(v0 - __half2float(h0)),
                               __float2half_rn(v1 - __half2float(h1))};
                __half2 ll1 = {__float2half_rn(v2 - __half2float(h2)),
                               __float2half_rn(v3 - __half2float(h3))};
                *(__half2*)(Ch0 + (long)gm * SE + gn)       = hh0;
                *(__half2*)(Ch0 + (long)(gm + 8) * SE + gn) = hh1;
                *(__half2*)(Ch1 + (long)gm * SE + gn)       = ll0;
                *(__half2*)(Ch1 + (long)(gm + 8) * SE + gn) = ll1;
            }
        }
    }
}

__global__ __launch_bounds__(256, 2)
void qkv_gemm_kernel(const float* __restrict__ bq, const float* __restrict__ bk,
                     const float* __restrict__ bv)
{
    const int z = blockIdx.z;
    const float* bias = (z == 0) ? bq : (z == 1) ? bk : bv;
    const int mode = (z == 0) ? 1 : (z == 1) ? 2 : 3;
    __half* c0 = (z == 0) ? g_q16 : (z == 1) ? g_k16 : g_vhi;
    mma_gemm_body(g_x16, g_w16 + (long)z * SE * SE, bias, mode,
                  nullptr, c0, g_vlo);
}

__global__ __launch_bounds__(256, 2)
void out_gemm_kernel(const float* __restrict__ bo, float* __restrict__ out)
{
    mma_gemm_body(g_a16, g_w16 + 3L * SE * SE, bo, 0, out, nullptr, nullptr);
}

// ---------------------------------------------------------------------------
// Tensor-core flash attention.
// CTA: 128 q rows x one (b,h). 8 warps, warp = 16 q rows. k-tile 64.
// QK^T: fp16 1-pass (Q prescaled by 1/8). PV: P fp16 1x, V hi+lo (2 passes).
// Mask via packed bitset. Online softmax in registers.
// SMEM: Q 16KB + 2 stages x (K 8KB + Vh 8KB + Vl 8KB) = 64KB.
// ---------------------------------------------------------------------------
#define AT_NT (SS / 64)
#define AT_SMEM 65536
#define QS_OFF 0
#define STG_OFF(s) (16384 + (s) * 24576)

// 64B-row swizzle for attention KV tiles (rows of 64 fp16 = 128B? no: 64 cols)
// K/V tiles are 64 rows x 64 cols fp16 = 128B per row. Reuse asw.

__global__ __launch_bounds__(256, 2)
void attn_kernel(const __half* __restrict__ Qg, const __half* __restrict__ Kg,
                 const __half* __restrict__ Vh, const __half* __restrict__ Vl,
                 __half* __restrict__ A16)
{
    extern __shared__ char dynsm[];
    const uint32_t sb = smem_u32(dynsm);
    const int tid  = threadIdx.x;
    const int lane = tid & 31;
    const int wid  = tid >> 5;
    const int q0   = blockIdx.x * 128;
    const int h    = blockIdx.y;
    const int b    = blockIdx.z;
    const int row0 = b * SS;
    const int col0 = h * SDK;
    const int wq0  = wid * 16;

    const unsigned long long* mb64 =
        reinterpret_cast<const unsigned long long*>(g_mb);
    const long mrow0 = ((long)(b * SS + q0 + wq0 + (lane >> 2))) * 32;

    {
        #pragma unroll
        for (int m = 0; m < 4; m++) {
            const int idx = m * 256 + tid;
            const int r = idx >> 3, c = idx & 7;
            cp_async16(asw(sb + QS_OFF, r, c),
                       Qg + (long)(row0 + q0 + r) * SE + col0 + c * 8);
        }
    }
    auto issue_kv = [&](int kt, int s) {
        const int k0 = kt * 64;
        const __half* srcs[3] = { Kg, Vh, Vl };
        #pragma unroll
        for (int m = 0; m < 6; m++) {
            const int idx = m * 256 + tid;
            const int mat = idx >> 9;
            const int wi  = idx & 511;
            const int r = wi >> 3, c = wi & 7;
            cp_async16(asw(sb + STG_OFF(s) + mat * 8192, r, c),
                       srcs[mat] + (long)(row0 + k0 + r) * SE + col0 + c * 8);
        }
    };
    issue_kv(0, 0);
    cp_commit();

    uint32_t qf[4][4];
    float oacc[8][4];
    float mrow[2] = {-3.0e38f, -3.0e38f};
    float lrow[2] = {0.0f, 0.0f};
    #pragma unroll
    for (int d = 0; d < 8; d++)
        #pragma unroll
        for (int k = 0; k < 4; k++) oacc[d][k] = 0.0f;

    for (int it = 0; it < AT_NT; ++it) {
        const int buf = it & 1;
        if (it + 1 < AT_NT) { issue_kv(it + 1, buf ^ 1); cp_commit(); cp_wait<1>(); }
        else                { cp_wait<0>(); }
        __syncthreads();

        if (it == 0) {
            #pragma unroll
            for (int ks = 0; ks < 4; ks++)
                ldm_x4(qf[ks], asw(sb + QS_OFF, wq0 + (lane & 15),
                                   ks * 2 + (lane >> 4)));
        }

        const uint32_t Kb  = sb + STG_OFF(buf);
        const uint32_t Vhb = Kb + 8192;
        const uint32_t Vlb = Kb + 16384;

        float sacc[8][4];
        #pragma unroll
        for (int nb = 0; nb < 8; nb++)
            #pragma unroll
            for (int k = 0; k < 4; k++) sacc[nb][k] = 0.0f;

        #pragma unroll
        for (int ks = 0; ks < 4; ks++) {
            uint32_t kf[4][4];
            const int br  = ((lane >> 4) << 3) + (lane & 7);
            const int bc  = ks * 2 + ((lane >> 3) & 1);
            #pragma unroll
            for (int p = 0; p < 4; p++)
                ldm_x4(kf[p], asw(Kb, p * 16 + br, bc));
            #pragma unroll
            for (int nb = 0; nb < 8; nb++)
                mma_fp16(sacc[nb], qf[ks], kf[nb >> 1][(nb & 1) * 2],
                         kf[nb >> 1][(nb & 1) * 2 + 1]);
        }

        unsigned long long mw0 = mb64[mrow0 + it];
        unsigned long long mw1 = mb64[mrow0 + 256 + it];
        #pragma unroll
        for (int i = 0; i < 2; i++) {
            const unsigned long long mw = i ? mw1 : mw0;
            float mx = -3.0e38f;
            #pragma unroll
            for (int nb = 0; nb < 8; nb++) {
                #pragma unroll
                for (int e = 0; e < 2; e++) {
                    const int bit = nb * 8 + ((lane & 3) << 1) + e;
                    float s = sacc[nb][2 * i + e];
                    s = ((mw >> bit) & 1ull) ? -1.0e9f : s;
                    sacc[nb][2 * i + e] = s;
                    mx = fmaxf(mx, s);
                }
            }
            mx = fmaxf(mx, __shfl_xor_sync(0xffffffffu, mx, 1));
            mx = fmaxf(mx, __shfl_xor_sync(0xffffffffu, mx, 2));
            const float mnew = fmaxf(mrow[i], mx);
            const float sc   = __expf(mrow[i] - mnew);
            mrow[i] = mnew;
            float sum = 0.0f;
            #pragma unroll
            for (int nb = 0; nb < 8; nb++) {
                #pragma unroll
                for (int e = 0; e < 2; e++) {
                    float p = __expf(sacc[nb][2 * i + e] - mnew);
                    sacc[nb][2 * i + e] = p;
                    sum += p;
                }
            }
            sum += __shfl_xor_sync(0xffffffffu, sum, 1);
            sum += __shfl_xor_sync(0xffffffffu, sum, 2);
            lrow[i] = lrow[i] * sc + sum;
            #pragma unroll
            for (int d = 0; d < 8; d++) {
                oacc[d][2 * i]     *= sc;
                oacc[d][2 * i + 1] *= sc;
            }
        }

        uint32_t pf[4][4];
        #pragma unroll
        for (int kk = 0; kk < 4; kk++) {
            pf[kk][0] = packh2(sacc[2 * kk][0],     sacc[2 * kk][1]);
            pf[kk][1] = packh2(sacc[2 * kk][2],     sacc[2 * kk][3]);
            pf[kk][2] = packh2(sacc[2 * kk + 1][0], sacc[2 * kk + 1][1]);
            pf[kk][3] = packh2(sacc[2 * kk + 1][2], sacc[2 * kk + 1][3]);
        }

        #pragma unroll
        for (int kk = 0; kk < 4; kk++) {
            const int vr = kk * 16 + (lane & 15);
            #pragma unroll
            for (int dp = 0; dp < 4; dp++) {
                const int vc = dp * 2 + (lane >> 4);
                uint32_t vf[4];
                ldm_x4_t(vf, asw(Vhb, vr, vc));
                mma_fp16(oacc[2 * dp],     pf[kk], vf[0], vf[1]);
                mma_fp16(oacc[2 * dp + 1], pf[kk], vf[2], vf[3]);
                ldm_x4_t(vf, asw(Vlb, vr, vc));
                mma_fp16(oacc[2 * dp],     pf[kk], vf[0], vf[1]);
                mma_fp16(oacc[2 * dp + 1], pf[kk], vf[2], vf[3]);
            }
        }
        __syncthreads();
    }

    #pragma unroll
    for (int i = 0; i < 2; i++) {
        const float inv = 1.0f / lrow[i];
        const long gq = row0 + q0 + wq0 + (lane >> 2) + 8 * i;
        #pragma unroll
        for (int d = 0; d < 8; d++) {
            const int gc = col0 + d * 8 + ((lane & 3) << 1);
            *(__half2*)(A16 + gq * SE + gc) =
                __floats2half2_rn(oacc[d][2 * i] * inv, oacc[d][2 * i + 1] * inv);
        }
    }
}

// ---------------------------------------------------------------------------
// Launch
// ---------------------------------------------------------------------------
extern "C" void kernel_launch(void* const* d_in, const int* in_sizes, int n_in,
                              void* d_out, int out_size)
{
    const float* x    = (const float*)d_in[0];
    const void*  mask = d_in[1];
    const float* Wq   = (const float*)d_in[2];
    const float* bq   = (const float*)d_in[3];
    const float* Wk   = (const float*)d_in[4];
    const float* bk   = (const float*)d_in[5];
    const float* Wv   = (const float*)d_in[6];
    const float* bv   = (const float*)d_in[7];
    const float* Wo   = (const float*)d_in[8];
    const float* bo   = (const float*)d_in[9];
    float* out = (float*)d_out;

    __half *x16, *a16, *w16, *q16, *k16, *vhi, *vlo;
    cudaGetSymbolAddress((void**)&x16, g_x16);
    cudaGetSymbolAddress((void**)&a16, g_a16);
    cudaGetSymbolAddress((void**)&w16, g_w16);
    cudaGetSymbolAddress((void**)&q16, g_q16);
    cudaGetSymbolAddress((void**)&k16, g_k16);
    cudaGetSymbolAddress((void**)&vhi, g_vhi);
    cudaGetSymbolAddress((void**)&vlo, g_vlo);

    cudaFuncSetAttribute(qkv_gemm_kernel,
                         cudaFuncAttributeMaxDynamicSharedMemorySize, GEMM_SMEM);
    cudaFuncSetAttribute(out_gemm_kernel,
                         cudaFuncAttributeMaxDynamicSharedMemorySize, GEMM_SMEM);
    cudaFuncSetAttribute(attn_kernel,
                         cudaFuncAttributeMaxDynamicSharedMemorySize, AT_SMEM);

    detect_mask_kind_kernel<<<1, 256>>>((const unsigned char*)mask);
    pack_mask_kernel<<<SB * SS * SS / 256, 256>>>(mask);

    const int nx = MTOT * SE;
    const int nw = SE * SE;
    tohalf_kernel<<<nx / 1024, 256>>>(x,  x16, nx);
    tohalf_kernel<<<nw / 1024, 256>>>(Wq, w16 + 0L * nw, nw);
    tohalf_kernel<<<nw / 1024, 256>>>(Wk, w16 + 1L * nw, nw);
    tohalf_kernel<<<nw / 1024, 256>>>(Wv, w16 + 2L * nw, nw);
    tohalf_kernel<<<nw / 1024, 256>>>(Wo, w16 + 3L * nw, nw);

    dim3 gqkv(SE / TN, MTOT / TM, 3);
    qkv_gemm_kernel<<<gqkv, 256, GEMM_SMEM>>>(bq, bk, bv);

    dim3 gat(SS / 128, SH, SB);
    attn_kernel<<<gat, 256, AT_SMEM>>>(q16, k16, vhi, vlo, a16);

    dim3 gout(SE / TN, MTOT / TM);
    out_gemm_kernel<<<gout, 256, GEMM_SMEM>>>(bo, out);
}